// round 5
// baseline (speedup 1.0000x reference)
#include <cuda_runtime.h>

typedef unsigned long long ull;

#define B_DIM    128
#define IN_DIM   1024
#define OUT_DIM  1024
#define KSPLIT   16
#define K_PER_CTA 64       // IN_DIM / KSPLIT
#define K_CHUNK  32        // smem stage depth (2 chunks)
#define O_TILE   128
#define THREADS  256
#define GRID     (KSPLIT * (OUT_DIM / O_TILE))   // 128 CTAs, one wave

// 8 MB fp32 partial sums: g_part[ks][b][o]
__device__ float g_part[KSPLIT * B_DIM * OUT_DIM];
__device__ unsigned int g_ctr;   // zero-init; monotonic across replays

__device__ __forceinline__ ull fma2(ull a, ull b, ull c) {
    ull d;
    asm("fma.rn.f32x2 %0, %1, %2, %3;" : "=l"(d) : "l"(a), "l"(b), "l"(c));
    return d;
}
__device__ __forceinline__ ull dup2(float w) {
    unsigned u = __float_as_uint(w);
    ull d;
    asm("mov.b64 %0, {%1, %1};" : "=l"(d) : "r"(u));
    return d;
}
__device__ __forceinline__ float lo32(ull v) { return __uint_as_float((unsigned)v); }
__device__ __forceinline__ float hi32(ull v) { return __uint_as_float((unsigned)(v >> 32)); }

// ---------------------------------------------------------------------------
// Fused persistent kernel.
//   grid 128 = 16 k-splits x 8 o-tiles. 256 threads. Microtile 8b x 8o.
//   acc packs o-PAIRS  -> w read as natural f32x2 pairs from ws (no dup movs)
//   x pre-duplicated in smem (xs_dup, ull) -> broadcast makes dup free.
// ---------------------------------------------------------------------------
__global__ void __launch_bounds__(THREADS, 1)
sic_fused(const float* __restrict__ x, const float* __restrict__ means,
          const float* __restrict__ bias, const int* __restrict__ dest,
          float* __restrict__ out)
{
    // 32 KB: xs_dup[kk][b] = {x,x} per b. Row = 128 ull. 16B-chunk swizzled (mask 63).
    __shared__ __align__(16) ull   xsd[K_CHUNK * B_DIM];
    // 16 KB: ws[kk][o] plain floats. Row = 128 f. 16B-chunk swizzled (mask 31).
    __shared__ __align__(16) float wsf[K_CHUNK * O_TILE];

    const int tid = threadIdx.x;
    const int ks  = blockIdx.x & (KSPLIT - 1);
    const int o0  = (blockIdx.x >> 4) * O_TILE;

    const int oc = tid & 15;    // o-chunk: outputs oc*8 .. oc*8+7
    const int bc = tid >> 4;    // b-chunk: batches bc*8 .. bc*8+7

    ull acc[32];   // acc[bi*4+op]: batch bc*8+bi, outputs (oc*8+2*op, +1)
#pragma unroll
    for (int i = 0; i < 32; i++) acc[i] = 0ull;

    for (int kc = 0; kc < K_PER_CTA / K_CHUNK; kc++) {
        const int k0 = ks * K_PER_CTA + kc * K_CHUNK;
        if (kc) __syncthreads();

        // ---- x chunk -> xs_dup (transposed, duplicated, swizzled) ----
        for (int s = tid; s < B_DIM * (K_CHUNK / 4); s += THREADS) {
            const int b  = s >> 3;
            const int kv = (s & 7) << 2;
            const float4 v = *reinterpret_cast<const float4*>(x + b * IN_DIM + k0 + kv);
            const int bh = b >> 1, bl = b & 1;
            xsd[(kv + 0) * B_DIM + ((((bh ^ (kv + 0)) & 63) << 1) | bl)] = dup2(v.x);
            xsd[(kv + 1) * B_DIM + ((((bh ^ (kv + 1)) & 63) << 1) | bl)] = dup2(v.y);
            xsd[(kv + 2) * B_DIM + ((((bh ^ (kv + 2)) & 63) << 1) | bl)] = dup2(v.z);
            xsd[(kv + 3) * B_DIM + ((((bh ^ (kv + 3)) & 63) << 1) | bl)] = dup2(v.w);
        }
        // ---- W chunk gather: ws[kk][o] = means[dest[(o0+o)*IN + k0+kk]] ----
        // o fixed per item -> the 4 means reads hit one 64B line (L1-friendly).
        for (int s = tid; s < O_TILE * (K_CHUNK / 4); s += THREADS) {
            const int o  = s & 127;
            const int kv = (s >> 7) << 2;
            const int4 dd = *reinterpret_cast<const int4*>(
                dest + (size_t)(o0 + o) * IN_DIM + k0 + kv);
            const int oh = o >> 2, ol = o & 3;
            wsf[(kv + 0) * O_TILE + ((((oh ^ (kv + 0)) & 31) << 2) | ol)] = means[dd.x];
            wsf[(kv + 1) * O_TILE + ((((oh ^ (kv + 1)) & 31) << 2) | ol)] = means[dd.y];
            wsf[(kv + 2) * O_TILE + ((((oh ^ (kv + 2)) & 31) << 2) | ol)] = means[dd.z];
            wsf[(kv + 3) * O_TILE + ((((oh ^ (kv + 3)) & 31) << 2) | ol)] = means[dd.w];
        }
        __syncthreads();

        // ---- main loop: 6 LDS + 32 FFMA2 per iter, zero MOVs ----
#pragma unroll
        for (int kk = 0; kk < K_CHUNK; kk++) {
            const ulonglong2 w01 = *reinterpret_cast<const ulonglong2*>(
                wsf + kk * O_TILE + (((((oc << 1)    ) ^ kk) & 31) << 2));
            const ulonglong2 w23 = *reinterpret_cast<const ulonglong2*>(
                wsf + kk * O_TILE + (((((oc << 1) | 1) ^ kk) & 31) << 2));
            ulonglong2 xq[4];
#pragma unroll
            for (int j = 0; j < 4; j++)
                xq[j] = *reinterpret_cast<const ulonglong2*>(
                    xsd + kk * B_DIM + (((((bc << 2) + j) ^ kk) & 63) << 1));
#pragma unroll
            for (int j = 0; j < 4; j++) {
                const ull xe = xq[j].x;   // dup x[b = bc*8 + 2j]
                const ull xo = xq[j].y;   // dup x[b = bc*8 + 2j + 1]
                acc[(2*j)*4 + 0] = fma2(xe, w01.x, acc[(2*j)*4 + 0]);
                acc[(2*j)*4 + 1] = fma2(xe, w01.y, acc[(2*j)*4 + 1]);
                acc[(2*j)*4 + 2] = fma2(xe, w23.x, acc[(2*j)*4 + 2]);
                acc[(2*j)*4 + 3] = fma2(xe, w23.y, acc[(2*j)*4 + 3]);
                acc[(2*j+1)*4 + 0] = fma2(xo, w01.x, acc[(2*j+1)*4 + 0]);
                acc[(2*j+1)*4 + 1] = fma2(xo, w01.y, acc[(2*j+1)*4 + 1]);
                acc[(2*j+1)*4 + 2] = fma2(xo, w23.x, acc[(2*j+1)*4 + 2]);
                acc[(2*j+1)*4 + 3] = fma2(xo, w23.y, acc[(2*j+1)*4 + 3]);
            }
        }
    }

    // ---- partials: per batch row, 2 contiguous float4 (o..o+7) ----
    {
        float* base = g_part + ((size_t)(ks * B_DIM + bc * 8)) * OUT_DIM + o0 + oc * 8;
#pragma unroll
        for (int bi = 0; bi < 8; bi++) {
            float4 f0, f1;
            f0.x = lo32(acc[bi*4+0]); f0.y = hi32(acc[bi*4+0]);
            f0.z = lo32(acc[bi*4+1]); f0.w = hi32(acc[bi*4+1]);
            f1.x = lo32(acc[bi*4+2]); f1.y = hi32(acc[bi*4+2]);
            f1.z = lo32(acc[bi*4+3]); f1.w = hi32(acc[bi*4+3]);
            *reinterpret_cast<float4*>(base + (size_t)bi * OUT_DIM)     = f0;
            *reinterpret_cast<float4*>(base + (size_t)bi * OUT_DIM + 4) = f1;
        }
    }

    // ---- device-wide barrier (monotonic counter: replay-safe) ----
    __threadfence();
    __syncthreads();
    if (tid == 0) {
        const unsigned val    = atomicAdd(&g_ctr, 1u) + 1u;
        const unsigned target = ((val - 1u) / GRID + 1u) * GRID;
        while (*(volatile unsigned*)&g_ctr < target) { }
    }
    __syncthreads();
    __threadfence();

    // ---- reduce: 32768 threads x float4; partials are L2-hot ----
    {
        const int gid = blockIdx.x * THREADS + tid;        // 0..32767
        const int off = gid * 4;                           // b*1024 + o
        const int o   = off & (OUT_DIM - 1);
        float4 a = make_float4(0.f, 0.f, 0.f, 0.f);
#pragma unroll
        for (int k = 0; k < KSPLIT; k++) {
            const float4 v = *reinterpret_cast<const float4*>(
                g_part + (size_t)k * (B_DIM * OUT_DIM) + off);
            a.x += v.x; a.y += v.y; a.z += v.z; a.w += v.w;
        }
        const float4 bb = *reinterpret_cast<const float4*>(bias + o);
        a.x += bb.x; a.y += bb.y; a.z += bb.z; a.w += bb.w;
        *reinterpret_cast<float4*>(out + off) = a;
    }
}

extern "C" void kernel_launch(void* const* d_in, const int* in_sizes, int n_in,
                              void* d_out, int out_size)
{
    (void)in_sizes; (void)n_in; (void)out_size;
    const float* x     = (const float*)d_in[0];   // [128,1024] f32
    const float* means = (const float*)d_in[1];   // [1024,16]  f32
    const float* bias  = (const float*)d_in[2];   // [1024]     f32
    // d_in[3] = col_idx (identity layout per row; unused)
    const int*   dest  = (const int*)d_in[4];     // [1024*1024] i32

    sic_fused<<<GRID, THREADS>>>(x, means, bias, dest, (float*)d_out);
}